// round 6
// baseline (speedup 1.0000x reference)
#include <cuda_runtime.h>
#include <cuda_fp16.h>
#include <cstdint>

#define B_DIM   512
#define IN_DIM  4096
#define OUT_DIM 11008
#define BK      32
#define NCHUNK  128
#define TILE_M  80
#define NTILES  138
#define THREADS 512

// SMEM layout (byte offsets from 1024-aligned base)
#define LUT_OFF 0            // 256 x 32 x 4B = 32KB replicated LUT
#define XS_OFF  32768        // 3 stages x (512 rows x 64B) = 3 x 32KB
#define WS_OFF  131072       // 3 stages x (80 rows x 128B int32) = 3 x 10KB
#define WF_OFF  161792       // 2 stages x (80 rows x 64B fp16) = 2 x 5KB
#define SMEM_BYTES (172032 + 1024)

__device__ __align__(16) __half g_xh[B_DIM * IN_DIM];
__device__ uint32_t g_lut[256];

// ---------------- helpers ----------------
__device__ __forceinline__ uint32_t smem_u32(const void* p) {
    uint32_t a;
    asm("{ .reg .u64 t; cvta.to.shared.u64 t, %1; cvt.u32.u64 %0, t; }" : "=r"(a) : "l"(p));
    return a;
}
__device__ __forceinline__ uint32_t lds32(uint32_t a) {
    uint32_t v;
    asm("ld.shared.b32 %0, [%1];" : "=r"(v) : "r"(a));
    return v;
}
__device__ __forceinline__ void lds128(uint32_t a, uint32_t& x, uint32_t& y, uint32_t& z, uint32_t& w) {
    asm("ld.shared.v4.b32 {%0,%1,%2,%3}, [%4];" : "=r"(x), "=r"(y), "=r"(z), "=r"(w) : "r"(a));
}
__device__ __forceinline__ void sts64(uint32_t a, uint32_t x, uint32_t y) {
    asm volatile("st.shared.v2.b32 [%0], {%1, %2};" :: "r"(a), "r"(x), "r"(y) : "memory");
}
__device__ __forceinline__ void cp16(uint32_t dst, const void* src) {
    asm volatile("cp.async.cg.shared.global [%0], [%1], 16;" :: "r"(dst), "l"(src) : "memory");
}
__device__ __forceinline__ void cp_commit() {
    asm volatile("cp.async.commit_group;" ::: "memory");
}
__device__ __forceinline__ void mma16816(float* c, const uint32_t* a, uint32_t b0, uint32_t b1) {
    asm volatile(
        "mma.sync.aligned.m16n8k16.row.col.f32.f16.f16.f32 "
        "{%0,%1,%2,%3}, {%4,%5,%6,%7}, {%8,%9}, {%0,%1,%2,%3};"
        : "+f"(c[0]), "+f"(c[1]), "+f"(c[2]), "+f"(c[3])
        : "r"(a[0]), "r"(a[1]), "r"(a[2]), "r"(a[3]), "r"(b0), "r"(b1));
}

// ---------------- prep: x fp32->fp16, exp LUT ----------------
__global__ void prep_kernel(const float* __restrict__ x,
                            const float* __restrict__ lmin,
                            const float* __restrict__ lmax) {
    int idx = blockIdx.x * blockDim.x + threadIdx.x;
    const int n4 = B_DIM * IN_DIM / 4;
    if (idx < n4) {
        float4 v = reinterpret_cast<const float4*>(x)[idx];
        __half2 a = __floats2half2_rn(v.x, v.y);
        __half2 b = __floats2half2_rn(v.z, v.w);
        uint2 w;
        w.x = *reinterpret_cast<uint32_t*>(&a);
        w.y = *reinterpret_cast<uint32_t*>(&b);
        reinterpret_cast<uint2*>(g_xh)[idx] = w;
    }
    if (blockIdx.x == 0 && threadIdx.x < 256) {
        float a = lmin[0], b = lmax[0];
        float nm = (255.0f - (float)threadIdx.x) / 254.0f;
        __half h = __float2half_rn(expf(fmaf(nm, b - a, a)));
        g_lut[threadIdx.x] = (uint32_t)__half_as_ushort(h);
    }
}

// ---------------- main GEMM ----------------
__global__ void __launch_bounds__(THREADS, 1)
qgemm_kernel(const int* __restrict__ stored, const int* __restrict__ sign,
             const float* __restrict__ scale, const float* __restrict__ bias,
             float* __restrict__ out) {
    extern __shared__ char smem_raw[];
    char* smem = (char*)(((uintptr_t)smem_raw + 1023) & ~(uintptr_t)1023);
    const uint32_t sb = smem_u32(smem);
    const int tid = threadIdx.x, wid = tid >> 5, lane = tid & 31;
    const int gid = lane >> 2, tig = lane & 3;
    const int o0 = blockIdx.x * TILE_M;

    // replicated LUT (bank == lane: conflict-free)
    uint32_t* slut = (uint32_t*)(smem + LUT_OFF);
    for (int i = tid; i < 256 * 32; i += THREADS) slut[i] = g_lut[i >> 5];
    const uint32_t* lut_lane = slut + lane;

    // acc: warp tile M80 x N32 -> 5 mtiles x 4 ntiles x 4 floats = 80 regs
    float acc[5][4][4];
#pragma unroll
    for (int mt = 0; mt < 5; mt++)
#pragma unroll
        for (int nt = 0; nt < 4; nt++)
#pragma unroll
            for (int i = 0; i < 4; i++) acc[mt][nt][i] = 0.0f;

    // MMA frag address constants (SW64: xor mask is gid-only)
    const uint32_t xorm = (uint32_t)(((gid >> 1) & 3) << 4);
    uint32_t coff[4];
#pragma unroll
    for (int j = 0; j < 4; j++) coff[j] = (uint32_t)(j * 16) ^ xorm;
    uint32_t baseA[5], baseB[4];
#pragma unroll
    for (int mt = 0; mt < 5; mt++) baseA[mt] = (uint32_t)((mt * 16 + gid) * 64 + tig * 4);
#pragma unroll
    for (int nt = 0; nt < 4; nt++) baseB[nt] = (uint32_t)((wid * 32 + nt * 8 + gid) * 64 + tig * 4);

    // W quad-units: cquad = tid&7 (4 ints), row0w = tid>>3 (0..63); j<2, j=1 only tid<128
    const int cquad = tid & 7, row0w = tid >> 3;
    uint32_t woff0, woff1;
    {
        int r0 = o0 + row0w;            if (r0 > OUT_DIM - 1) r0 = OUT_DIM - 1;
        int r1 = o0 + row0w + 64;       if (r1 > OUT_DIM - 1) r1 = OUT_DIM - 1;
        woff0 = (uint32_t)r0 * IN_DIM + (uint32_t)(cquad * 4);
        woff1 = (uint32_t)r1 * IN_DIM + (uint32_t)(cquad * 4);
    }
    const uint32_t wsdst0 = (uint32_t)(row0w * 128 + cquad * 16);           // +8192 for j=1
    const uint32_t wfdst0 = (uint32_t)(row0w * 64) +
        (((uint32_t)(cquad * 8)) ^ ((uint32_t)((row0w >> 1) & 3) << 4));    // +4096 for j=1
    const bool w1 = (tid < 128);

    // X units: sg = tid&3 (16B), bx = tid>>2 (0..127); j<4, strides 128*IN_DIM / 8192
    const int sg = tid & 3, bx = tid >> 2;
    const uint32_t xoff0 = (uint32_t)bx * IN_DIM + (uint32_t)(sg * 8);
    const uint32_t xdst0 = (uint32_t)(bx * 64) +
        (((uint32_t)(sg * 16)) ^ ((uint32_t)((bx >> 1) & 3) << 4));

    // ---------------- prologue ----------------
#pragma unroll
    for (int j = 0; j < 4; j++)
        cp16(sb + XS_OFF + xdst0 + j * 8192, g_xh + xoff0 + (size_t)j * 128 * IN_DIM);
    cp_commit();                                            // X(0)
    cp16(sb + WS_OFF + wsdst0, stored + woff0);
    if (w1) cp16(sb + WS_OFF + wsdst0 + 8192, stored + woff1);
    cp_commit();                                            // Ws(0)
    cp16(sb + WS_OFF + 10240 + wsdst0, stored + woff0 + BK);
    if (w1) cp16(sb + WS_OFF + 10240 + wsdst0 + 8192, stored + woff1 + BK);
    cp_commit();                                            // Ws(1)
    uint4 rg0 = *(const uint4*)(sign + woff0);
    uint4 rg1 = w1 ? *(const uint4*)(sign + woff1) : make_uint4(0, 0, 0, 0);
    asm volatile("cp.async.wait_group 1;" ::: "memory");    // X(0), Ws(0) done
    __syncthreads();                                        // publish (+ LUT)
    {   // dequant(0) -> Wf[0]
        uint32_t s0, s1, s2, s3x;
        lds128(sb + WS_OFF + wsdst0, s0, s1, s2, s3x);
        uint32_t h0 = lut_lane[s0 << 5] | (rg0.x & 0x8000u);
        uint32_t h1 = lut_lane[s1 << 5] | (rg0.y & 0x8000u);
        uint32_t h2 = lut_lane[s2 << 5] | (rg0.z & 0x8000u);
        uint32_t h3 = lut_lane[s3x << 5] | (rg0.w & 0x8000u);
        sts64(sb + WF_OFF + wfdst0, h0 | (h1 << 16), h2 | (h3 << 16));
        if (w1) {
            lds128(sb + WS_OFF + wsdst0 + 8192, s0, s1, s2, s3x);
            h0 = lut_lane[s0 << 5] | (rg1.x & 0x8000u);
            h1 = lut_lane[s1 << 5] | (rg1.y & 0x8000u);
            h2 = lut_lane[s2 << 5] | (rg1.z & 0x8000u);
            h3 = lut_lane[s3x << 5] | (rg1.w & 0x8000u);
            sts64(sb + WF_OFF + wfdst0 + 4096, h0 | (h1 << 16), h2 | (h3 << 16));
        }
    }

    int s3 = 0, s3b = 1, s3c = 2;
#pragma unroll 1
    for (int k = 0; k < NCHUNK; k++) {
        if (k + 1 < NCHUNK) {
            const uint32_t K1 = (uint32_t)(k + 1) * BK;
            const uint32_t xd = sb + XS_OFF + (uint32_t)s3b * 32768;
#pragma unroll
            for (int j = 0; j < 4; j++)
                cp16(xd + xdst0 + j * 8192, g_xh + xoff0 + (size_t)j * 128 * IN_DIM + K1);
            cp_commit();
        }
        if (k + 2 < NCHUNK) {
            const uint32_t K2 = (uint32_t)(k + 2) * BK;
            const uint32_t wd = sb + WS_OFF + (uint32_t)s3c * 10240;
            cp16(wd + wsdst0, stored + woff0 + K2);
            if (w1) cp16(wd + wsdst0 + 8192, stored + woff1 + K2);
            cp_commit();
        }
        if (k + 1 < NCHUNK) {
            const uint32_t K1 = (uint32_t)(k + 1) * BK;
            rg0 = *(const uint4*)(sign + woff0 + K1);
            if (w1) rg1 = *(const uint4*)(sign + woff1 + K1);
        }
        if (k + 2 < NCHUNK)      asm volatile("cp.async.wait_group 2;" ::: "memory");
        else if (k + 1 < NCHUNK) asm volatile("cp.async.wait_group 1;" ::: "memory");
        else                     asm volatile("cp.async.wait_group 0;" ::: "memory");
        __syncthreads();

        // MMA(k)
        {
            const uint32_t wfs = sb + WF_OFF + (uint32_t)(k & 1) * 5120;
            const uint32_t xss = sb + XS_OFF + (uint32_t)s3 * 32768;
#pragma unroll
            for (int kk = 0; kk < 2; kk++) {
                uint32_t a[5][4];
#pragma unroll
                for (int mt = 0; mt < 5; mt++) {
                    a[mt][0] = lds32(wfs + baseA[mt] + coff[2 * kk]);
                    a[mt][1] = lds32(wfs + baseA[mt] + 512 + coff[2 * kk]);
                    a[mt][2] = lds32(wfs + baseA[mt] + coff[2 * kk + 1]);
                    a[mt][3] = lds32(wfs + baseA[mt] + 512 + coff[2 * kk + 1]);
                }
#pragma unroll
                for (int nt = 0; nt < 4; nt++) {
                    uint32_t b0 = lds32(xss + baseB[nt] + coff[2 * kk]);
                    uint32_t b1 = lds32(xss + baseB[nt] + coff[2 * kk + 1]);
#pragma unroll
                    for (int mt = 0; mt < 5; mt++) mma16816(acc[mt][nt], a[mt], b0, b1);
                }
            }
        }

        // dequant(k+1) -> Wf[(k+1)&1]
        if (k + 1 < NCHUNK) {
            const uint32_t wsb = sb + WS_OFF + (uint32_t)s3b * 10240;
            const uint32_t wfb = sb + WF_OFF + (uint32_t)((k + 1) & 1) * 5120;
            uint32_t s0, s1, s2, s3x;
            lds128(wsb + wsdst0, s0, s1, s2, s3x);
            uint32_t h0 = lut_lane[s0 << 5] | (rg0.x & 0x8000u);
            uint32_t h1 = lut_lane[s1 << 5] | (rg0.y & 0x8000u);
            uint32_t h2 = lut_lane[s2 << 5] | (rg0.z & 0x8000u);
            uint32_t h3 = lut_lane[s3x << 5] | (rg0.w & 0x8000u);
            sts64(wfb + wfdst0, h0 | (h1 << 16), h2 | (h3 << 16));
            if (w1) {
                lds128(wsb + wsdst0 + 8192, s0, s1, s2, s3x);
                h0 = lut_lane[s0 << 5] | (rg1.x & 0x8000u);
                h1 = lut_lane[s1 << 5] | (rg1.y & 0x8000u);
                h2 = lut_lane[s2 << 5] | (rg1.z & 0x8000u);
                h3 = lut_lane[s3x << 5] | (rg1.w & 0x8000u);
                sts64(wfb + wfdst0 + 4096, h0 | (h1 << 16), h2 | (h3 << 16));
            }
        }

        int t = s3; s3 = s3b; s3b = s3c; s3c = t;
    }

    // ---------------- epilogue ----------------
#pragma unroll
    for (int mt = 0; mt < 5; mt++) {
        int o_lo = o0 + mt * 16 + gid;
        int o_hi = o_lo + 8;
        int cl = o_lo < OUT_DIM ? o_lo : OUT_DIM - 1;
        int ch = o_hi < OUT_DIM ? o_hi : OUT_DIM - 1;
        float blo = bias[cl], slo = scale[cl];
        float bhi = bias[ch], shi = scale[ch];
#pragma unroll
        for (int nt = 0; nt < 4; nt++) {
            int b = wid * 32 + nt * 8 + tig * 2;
            float* p0 = out + (size_t)b * OUT_DIM;
            float* p1 = p0 + OUT_DIM;
            if (o_lo < OUT_DIM) {
                p0[o_lo] = (acc[mt][nt][0] + blo) * slo;
                p1[o_lo] = (acc[mt][nt][1] + blo) * slo;
            }
            if (o_hi < OUT_DIM) {
                p0[o_hi] = (acc[mt][nt][2] + bhi) * shi;
                p1[o_hi] = (acc[mt][nt][3] + bhi) * shi;
            }
        }
    }
}

extern "C" void kernel_launch(void* const* d_in, const int* in_sizes, int n_in,
                              void* d_out, int out_size) {
    const float* x      = (const float*)d_in[0];
    const int*   stored = (const int*)d_in[1];
    const int*   sign   = (const int*)d_in[2];
    const float* lmin   = (const float*)d_in[3];
    const float* lmax   = (const float*)d_in[4];
    const float* scale  = (const float*)d_in[5];
    const float* bias   = (const float*)d_in[6];
    float* out = (float*)d_out;

    prep_kernel<<<(B_DIM * IN_DIM / 4 + 255) / 256, 256>>>(x, lmin, lmax);

    cudaFuncSetAttribute(qgemm_kernel,
                         cudaFuncAttributeMaxDynamicSharedMemorySize, SMEM_BYTES);
    qgemm_kernel<<<NTILES, THREADS, SMEM_BYTES>>>(stored, sign, scale, bias, out);
}

// round 8
// speedup vs baseline: 1.1925x; 1.1925x over previous
#include <cuda_runtime.h>
#include <cuda_fp16.h>
#include <cstdint>

#define B_DIM   512
#define IN_DIM  4096
#define OUT_DIM 11008
#define BK      32
#define NCHUNK  128
#define TILE_M  80
#define NTILES  138
#define THREADS 256

// SMEM layout (byte offsets from 1024-aligned base)
#define LUT_OFF 0            // 256 x 32 x 4B = 32KB replicated LUT
#define WS_OFF  32768        // 3 stages x (80 rows x 128B int32) = 3 x 10KB
#define WF_OFF  63488        // 2 stages x (80 rows x 64B fp16) = 2 x 5KB
#define SMEM_BYTES (73728 + 1024)

// fragment-permuted fp16 x: per (batch, kblock32) the 32 halves are reordered
// so one uint4 per (batch,kc,tig) = both kk16 B-fragments (b0,b1) x 2
__device__ __align__(16) __half g_xp[B_DIM * IN_DIM];
__device__ uint32_t g_lut[256];

// ---------------- helpers ----------------
__device__ __forceinline__ uint32_t smem_u32(const void* p) {
    uint32_t a;
    asm("{ .reg .u64 t; cvta.to.shared.u64 t, %1; cvt.u32.u64 %0, t; }" : "=r"(a) : "l"(p));
    return a;
}
__device__ __forceinline__ uint32_t lds32(uint32_t a) {
    uint32_t v;
    asm("ld.shared.b32 %0, [%1];" : "=r"(v) : "r"(a));
    return v;
}
__device__ __forceinline__ void lds64(uint32_t a, uint32_t& x, uint32_t& y) {
    asm("ld.shared.v2.b32 {%0,%1}, [%2];" : "=r"(x), "=r"(y) : "r"(a));
}
__device__ __forceinline__ void sts32(uint32_t a, uint32_t v) {
    asm volatile("st.shared.b32 [%0], %1;" :: "r"(a), "r"(v) : "memory");
}
__device__ __forceinline__ void cp8(uint32_t dst, const void* src) {
    asm volatile("cp.async.ca.shared.global [%0], [%1], 8;" :: "r"(dst), "l"(src) : "memory");
}
__device__ __forceinline__ void cp_commit() {
    asm volatile("cp.async.commit_group;" ::: "memory");
}
__device__ __forceinline__ void mma16816(float* c, const uint32_t* a, uint32_t b0, uint32_t b1) {
    asm volatile(
        "mma.sync.aligned.m16n8k16.row.col.f32.f16.f16.f32 "
        "{%0,%1,%2,%3}, {%4,%5,%6,%7}, {%8,%9}, {%0,%1,%2,%3};"
        : "+f"(c[0]), "+f"(c[1]), "+f"(c[2]), "+f"(c[3])
        : "r"(a[0]), "r"(a[1]), "r"(a[2]), "r"(a[3]), "r"(b0), "r"(b1));
}

// ---------------- prep: x fp32 -> fragment-permuted fp16 + exp LUT ----------------
// unit idx -> (b, kc, tig): dst uint4 = g_xp halves [b*4096 + kc*32 + tig*8 .. +7]
// source floats: b*4096 + kc*32 + {2t,2t+1, 8+2t,8+2t+1, 16+2t,16+2t+1, 24+2t,24+2t+1}
__global__ void prep_kernel(const float* __restrict__ x,
                            const float* __restrict__ lmin,
                            const float* __restrict__ lmax) {
    int idx = blockIdx.x * blockDim.x + threadIdx.x;
    const int nunits = B_DIM * IN_DIM / 8;   // 262144
    if (idx < nunits) {
        int tig = idx & 3, kc = (idx >> 2) & 127, b = idx >> 9;
        const float* src = x + (size_t)b * IN_DIM + kc * 32 + tig * 2;
        float2 f0 = *(const float2*)(src);
        float2 f1 = *(const float2*)(src + 8);
        float2 f2 = *(const float2*)(src + 16);
        float2 f3 = *(const float2*)(src + 24);
        __half2 h0 = __floats2half2_rn(f0.x, f0.y);
        __half2 h1 = __floats2half2_rn(f1.x, f1.y);
        __half2 h2 = __floats2half2_rn(f2.x, f2.y);
        __half2 h3 = __floats2half2_rn(f3.x, f3.y);
        uint4 v;
        v.x = *reinterpret_cast<uint32_t*>(&h0);
        v.y = *reinterpret_cast<uint32_t*>(&h1);
        v.z = *reinterpret_cast<uint32_t*>(&h2);
        v.w = *reinterpret_cast<uint32_t*>(&h3);
        reinterpret_cast<uint4*>(g_xp)[idx] = v;
    }
    if (blockIdx.x == 0 && threadIdx.x < 256) {
        float a = lmin[0], b = lmax[0];
        float nm = (255.0f - (float)threadIdx.x) / 254.0f;
        __half h = __float2half_rn(expf(fmaf(nm, b - a, a)));
        g_lut[threadIdx.x] = (uint32_t)__half_as_ushort(h);
    }
}

// ---------------- main GEMM ----------------
__global__ void __launch_bounds__(THREADS, 1)
qgemm_kernel(const int* __restrict__ stored, const int* __restrict__ sign,
             const float* __restrict__ scale, const float* __restrict__ bias,
             float* __restrict__ out) {
    extern __shared__ char smem_raw[];
    char* smem = (char*)(((uintptr_t)smem_raw + 1023) & ~(uintptr_t)1023);
    const uint32_t sb = smem_u32(smem);
    const int tid = threadIdx.x, wid = tid >> 5, lane = tid & 31;
    const int gid = lane >> 2, tig = lane & 3;
    const int o0 = blockIdx.x * TILE_M;
    const int n0 = wid * 64;

    // replicated LUT (bank == lane: conflict-free)
    uint32_t* slut = (uint32_t*)(smem + LUT_OFF);
    for (int i = tid; i < 256 * 32; i += THREADS) slut[i] = g_lut[i >> 5];
    const uint32_t* lut_lane = slut + lane;

    float acc[5][8][4];
#pragma unroll
    for (int mt = 0; mt < 5; mt++)
#pragma unroll
        for (int nt = 0; nt < 8; nt++)
#pragma unroll
            for (int i = 0; i < 4; i++) acc[mt][nt][i] = 0.0f;

    // A-frag address constants (R5-verbatim; SW64 xor mask is gid-only)
    const uint32_t xorm = (uint32_t)(((gid >> 1) & 3) << 4);
    uint32_t coff[4];
#pragma unroll
    for (int j = 0; j < 4; j++) coff[j] = (uint32_t)(j * 16) ^ xorm;
    uint32_t baseA[5];
#pragma unroll
    for (int mt = 0; mt < 5; mt++) baseA[mt] = (uint32_t)((mt * 16 + gid) * 64 + tig * 4);

    // B: direct from fragment-permuted global (L2-resident); per-lane base
    const __half* pB = g_xp + (size_t)(n0 + gid) * IN_DIM + tig * 8;

    // W unit coords (R5-verbatim): u = tid + j*256 -> row (0..79), pair (0..15 of 2 ints)
    uint32_t woff[5], wsdst[5], wfdst[5];
#pragma unroll
    for (int j = 0; j < 5; j++) {
        int u = tid + j * 256, row = u >> 4, cp = u & 15;
        int rowg = o0 + row;
        if (rowg > OUT_DIM - 1) rowg = OUT_DIM - 1;
        woff[j]  = (uint32_t)rowg * IN_DIM + (uint32_t)(cp * 2);
        wsdst[j] = (uint32_t)(row * 128 + cp * 8);
        wfdst[j] = (uint32_t)(row * 64) + ((uint32_t)(cp * 4) ^ (uint32_t)(((row >> 1) & 3) << 4));
    }

    // ---------------- prologue: Ws(0), Ws(1), sign(0), dequant(0) ----------------
#pragma unroll
    for (int j = 0; j < 5; j++) cp8(sb + WS_OFF + wsdst[j], stored + woff[j]);
    cp_commit();                                            // Ws(0)
#pragma unroll
    for (int j = 0; j < 5; j++) cp8(sb + WS_OFF + 10240 + wsdst[j], stored + woff[j] + BK);
    cp_commit();                                            // Ws(1)
    uint2 rg[5];
#pragma unroll
    for (int j = 0; j < 5; j++) rg[j] = *(const uint2*)(sign + woff[j]);
    asm volatile("cp.async.wait_group 1;" ::: "memory");    // Ws(0) done
    __syncthreads();                                        // publish Ws(0) + LUT
    {
        const uint32_t wsb = sb + WS_OFF, wfb = sb + WF_OFF;
#pragma unroll
        for (int j = 0; j < 5; j++) {
            uint32_t s0, s1;
            lds64(wsb + wsdst[j], s0, s1);
            uint32_t h0 = lut_lane[s0 << 5] | (rg[j].x & 0x8000u);
            uint32_t h1 = lut_lane[s1 << 5] | (rg[j].y & 0x8000u);
            sts32(wfb + wfdst[j], h0 | (h1 << 16));
        }
    }

    int s3 = 0, s3b = 1, s3c = 2;   // Ws stage rotation: k, k+1, k+2
#pragma unroll 1
    for (int k = 0; k < NCHUNK; k++) {
        // B-frags for chunk k: 8 coalesced LDG.128/warp from L2, issued early
        uint4 bx[8];
        {
            const __half* pk = pB + (uint32_t)k * 32;
#pragma unroll
            for (int nt = 0; nt < 8; nt++)
                bx[nt] = *(const uint4*)(pk + (size_t)nt * 8 * IN_DIM);
        }
        // Ws(k+2) copies
        if (k + 2 < NCHUNK) {
            const uint32_t K2 = (uint32_t)(k + 2) * BK;
            const uint32_t wd = sb + WS_OFF + (uint32_t)s3c * 10240;
#pragma unroll
            for (int j = 0; j < 5; j++) cp8(wd + wsdst[j], stored + woff[j] + K2);
            cp_commit();
        }
        // sign(k+1)
        if (k + 1 < NCHUNK) {
            const uint32_t K1 = (uint32_t)(k + 1) * BK;
#pragma unroll
            for (int j = 0; j < 5; j++) rg[j] = *(const uint2*)(sign + woff[j] + K1);
        }
        if (k + 2 < NCHUNK)      asm volatile("cp.async.wait_group 1;" ::: "memory");
        else if (k + 1 < NCHUNK) asm volatile("cp.async.wait_group 0;" ::: "memory");
        __syncthreads();   // publish Wf(k) [written last iter] + Ws(k+1)

        // MMA(k): A via lds32 (R5-verbatim), B from registers
        {
            const uint32_t wfs = sb + WF_OFF + (uint32_t)(k & 1) * 5120;
#pragma unroll
            for (int kk = 0; kk < 2; kk++) {
                uint32_t a[5][4];
#pragma unroll
                for (int mt = 0; mt < 5; mt++) {
                    a[mt][0] = lds32(wfs + baseA[mt] + coff[2 * kk]);
                    a[mt][1] = lds32(wfs + baseA[mt] + 512 + coff[2 * kk]);
                    a[mt][2] = lds32(wfs + baseA[mt] + coff[2 * kk + 1]);
                    a[mt][3] = lds32(wfs + baseA[mt] + 512 + coff[2 * kk + 1]);
                }
#pragma unroll
                for (int nt = 0; nt < 8; nt++) {
                    uint32_t b0 = kk ? bx[nt].z : bx[nt].x;
                    uint32_t b1 = kk ? bx[nt].w : bx[nt].y;
#pragma unroll
                    for (int mt = 0; mt < 5; mt++) mma16816(acc[mt][nt], a[mt], b0, b1);
                }
            }
        }

        // dequant(k+1) -> Wf[(k+1)&1]
        if (k + 1 < NCHUNK) {
            const uint32_t wsb = sb + WS_OFF + (uint32_t)s3b * 10240;
            const uint32_t wfb = sb + WF_OFF + (uint32_t)((k + 1) & 1) * 5120;
#pragma unroll
            for (int j = 0; j < 5; j++) {
                uint32_t s0, s1;
                lds64(wsb + wsdst[j], s0, s1);
                uint32_t h0 = lut_lane[s0 << 5] | (rg[j].x & 0x8000u);
                uint32_t h1 = lut_lane[s1 << 5] | (rg[j].y & 0x8000u);
                sts32(wfb + wfdst[j], h0 | (h1 << 16));
            }
        }

        int t = s3; s3 = s3b; s3b = s3c; s3c = t;
    }

    // ---------------- epilogue ----------------
#pragma unroll
    for (int mt = 0; mt < 5; mt++) {
        int o_lo = o0 + mt * 16 + gid;
        int o_hi = o_lo + 8;
        int cl = o_lo < OUT_DIM ? o_lo : OUT_DIM - 1;
        int ch = o_hi < OUT_DIM ? o_hi : OUT_DIM - 1;
        float blo = bias[cl], slo = scale[cl];
        float bhi = bias[ch], shi = scale[ch];
#pragma unroll
        for (int nt = 0; nt < 8; nt++) {
            int b = n0 + nt * 8 + tig * 2;
            float* p0 = out + (size_t)b * OUT_DIM;
            float* p1 = p0 + OUT_DIM;
            if (o_lo < OUT_DIM) {
                p0[o_lo] = (acc[mt][nt][0] + blo) * slo;
                p1[o_lo] = (acc[mt][nt][1] + blo) * slo;
            }
            if (o_hi < OUT_DIM) {
                p0[o_hi] = (acc[mt][nt][2] + bhi) * shi;
                p1[o_hi] = (acc[mt][nt][3] + bhi) * shi;
            }
        }
    }
}

extern "C" void kernel_launch(void* const* d_in, const int* in_sizes, int n_in,
                              void* d_out, int out_size) {
    const float* x      = (const float*)d_in[0];
    const int*   stored = (const int*)d_in[1];
    const int*   sign   = (const int*)d_in[2];
    const float* lmin   = (const float*)d_in[3];
    const float* lmax   = (const float*)d_in[4];
    const float* scale  = (const float*)d_in[5];
    const float* bias   = (const float*)d_in[6];
    float* out = (float*)d_out;

    prep_kernel<<<(B_DIM * IN_DIM / 8 + 255) / 256, 256>>>(x, lmin, lmax);

    cudaFuncSetAttribute(qgemm_kernel,
                         cudaFuncAttributeMaxDynamicSharedMemorySize, SMEM_BYTES);
    qgemm_kernel<<<NTILES, THREADS, SMEM_BYTES>>>(stored, sign, scale, bias, out);
}

// round 9
// speedup vs baseline: 1.4739x; 1.2360x over previous
#include <cuda_runtime.h>
#include <cuda_fp16.h>
#include <cstdint>

#define B_DIM   512
#define IN_DIM  4096
#define OUT_DIM 11008
#define BK      32
#define NCHUNK  128
#define TILE_M  80
#define NTILES  138
#define THREADS 512

// SMEM layout (byte offsets from 1024-aligned base)
#define LUT_OFF 0            // 256 x 32 x 4B = 32KB replicated LUT
#define WS_OFF  32768        // 3 stages x (80 rows x 128B int32) = 3 x 10KB
#define WF_OFF  63488        // 2 stages x (80 rows x 64B fp16) = 2 x 5KB
#define SMEM_BYTES (73728 + 1024)

// chunk-major fragment-permuted fp16 x:
// half offset = kc*16384 + b*32 + slot  (slot = mma-B fragment order within k32)
__device__ __align__(16) __half g_xp2[B_DIM * IN_DIM];
__device__ uint32_t g_lut[256];

// ---------------- helpers ----------------
__device__ __forceinline__ uint32_t smem_u32(const void* p) {
    uint32_t a;
    asm("{ .reg .u64 t; cvta.to.shared.u64 t, %1; cvt.u32.u64 %0, t; }" : "=r"(a) : "l"(p));
    return a;
}
__device__ __forceinline__ uint32_t lds32(uint32_t a) {
    uint32_t v;
    asm("ld.shared.b32 %0, [%1];" : "=r"(v) : "r"(a));
    return v;
}
__device__ __forceinline__ void lds128(uint32_t a, uint32_t& x, uint32_t& y, uint32_t& z, uint32_t& w) {
    asm("ld.shared.v4.b32 {%0,%1,%2,%3}, [%4];" : "=r"(x), "=r"(y), "=r"(z), "=r"(w) : "r"(a));
}
__device__ __forceinline__ void sts64(uint32_t a, uint32_t x, uint32_t y) {
    asm volatile("st.shared.v2.b32 [%0], {%1, %2};" :: "r"(a), "r"(x), "r"(y) : "memory");
}
__device__ __forceinline__ void cp16(uint32_t dst, const void* src) {
    asm volatile("cp.async.cg.shared.global [%0], [%1], 16;" :: "r"(dst), "l"(src) : "memory");
}
__device__ __forceinline__ void cp_commit() {
    asm volatile("cp.async.commit_group;" ::: "memory");
}
__device__ __forceinline__ void mma16816(float* c, const uint32_t* a, uint32_t b0, uint32_t b1) {
    asm volatile(
        "mma.sync.aligned.m16n8k16.row.col.f32.f16.f16.f32 "
        "{%0,%1,%2,%3}, {%4,%5,%6,%7}, {%8,%9}, {%0,%1,%2,%3};"
        : "+f"(c[0]), "+f"(c[1]), "+f"(c[2]), "+f"(c[3])
        : "r"(a[0]), "r"(a[1]), "r"(a[2]), "r"(a[3]), "r"(b0), "r"(b1));
}

// ---------------- prep: x fp32 -> chunk-major permuted fp16 + exp LUT ----------------
// idx = (kc*512 + b)*4 + tig ; dst uint4 at g_xp2 + idx*8 halves
// src floats: x[b*4096 + kc*32 + tig*2 + {0,1, 8,9, 16,17, 24,25}]
__global__ void prep_kernel(const float* __restrict__ x,
                            const float* __restrict__ lmin,
                            const float* __restrict__ lmax) {
    int idx = blockIdx.x * blockDim.x + threadIdx.x;
    const int nunits = B_DIM * IN_DIM / 8;   // 262144
    if (idx < nunits) {
        int tig = idx & 3, b = (idx >> 2) & 511, kc = idx >> 11;
        const float* src = x + (size_t)b * IN_DIM + kc * 32 + tig * 2;
        float2 f0 = *(const float2*)(src);
        float2 f1 = *(const float2*)(src + 8);
        float2 f2 = *(const float2*)(src + 16);
        float2 f3 = *(const float2*)(src + 24);
        __half2 h0 = __floats2half2_rn(f0.x, f0.y);
        __half2 h1 = __floats2half2_rn(f1.x, f1.y);
        __half2 h2 = __floats2half2_rn(f2.x, f2.y);
        __half2 h3 = __floats2half2_rn(f3.x, f3.y);
        uint4 v;
        v.x = *reinterpret_cast<uint32_t*>(&h0);
        v.y = *reinterpret_cast<uint32_t*>(&h1);
        v.z = *reinterpret_cast<uint32_t*>(&h2);
        v.w = *reinterpret_cast<uint32_t*>(&h3);
        reinterpret_cast<uint4*>(g_xp2)[idx] = v;
    }
    if (blockIdx.x == 0 && threadIdx.x < 256) {
        float a = lmin[0], b = lmax[0];
        float nm = (255.0f - (float)threadIdx.x) / 254.0f;
        __half h = __float2half_rn(expf(fmaf(nm, b - a, a)));
        g_lut[threadIdx.x] = (uint32_t)__half_as_ushort(h);
    }
}

// ---------------- main GEMM ----------------
__global__ void __launch_bounds__(THREADS, 1)
qgemm_kernel(const int* __restrict__ stored, const int* __restrict__ sign,
             const float* __restrict__ scale, const float* __restrict__ bias,
             float* __restrict__ out) {
    extern __shared__ char smem_raw[];
    char* smem = (char*)(((uintptr_t)smem_raw + 1023) & ~(uintptr_t)1023);
    const uint32_t sb = smem_u32(smem);
    const int tid = threadIdx.x, wid = tid >> 5, lane = tid & 31;
    const int gid = lane >> 2, tig = lane & 3;
    const int o0 = blockIdx.x * TILE_M;
    const int n0 = wid * 32;          // warp N tile = 32 batch rows

    // replicated LUT (bank == lane: conflict-free)
    uint32_t* slut = (uint32_t*)(smem + LUT_OFF);
    for (int i = tid; i < 256 * 32; i += THREADS) slut[i] = g_lut[i >> 5];
    const uint32_t* lut_lane = slut + lane;

    // acc: warp tile M80 x N32 -> 5 mtiles x 4 ntiles x 4 floats = 80 regs
    float acc[5][4][4];
#pragma unroll
    for (int mt = 0; mt < 5; mt++)
#pragma unroll
        for (int nt = 0; nt < 4; nt++)
#pragma unroll
            for (int i = 0; i < 4; i++) acc[mt][nt][i] = 0.0f;

    // A-frag address constants (R5-proven; SW64 xor mask is gid-only)
    const uint32_t xorm = (uint32_t)(((gid >> 1) & 3) << 4);
    uint32_t coff[4];
#pragma unroll
    for (int j = 0; j < 4; j++) coff[j] = (uint32_t)(j * 16) ^ xorm;
    uint32_t baseA[5];
#pragma unroll
    for (int mt = 0; mt < 5; mt++) baseA[mt] = (uint32_t)((mt * 16 + gid) * 64 + tig * 4);

    // B: chunk-major permuted global; warp block contiguous 2KB/chunk
    const __half* pB = g_xp2 + (uint32_t)(n0 + gid) * 32 + (uint32_t)(tig * 8);

    // W quad-units (R6-proven): cquad = tid&7, row0w = tid>>3 (0..63); j=1 only tid<128
    const int cquad = tid & 7, row0w = tid >> 3;
    uint32_t woff0, woff1;
    {
        int r0 = o0 + row0w;        if (r0 > OUT_DIM - 1) r0 = OUT_DIM - 1;
        int r1 = o0 + row0w + 64;   if (r1 > OUT_DIM - 1) r1 = OUT_DIM - 1;
        woff0 = (uint32_t)r0 * IN_DIM + (uint32_t)(cquad * 4);
        woff1 = (uint32_t)r1 * IN_DIM + (uint32_t)(cquad * 4);
    }
    const uint32_t wsdst0 = (uint32_t)(row0w * 128 + cquad * 16);           // +8192 for j=1
    const uint32_t wfdst0 = (uint32_t)(row0w * 64) +
        (((uint32_t)(cquad * 8)) ^ ((uint32_t)((row0w >> 1) & 3) << 4));    // +4096 for j=1
    const bool w1 = (tid < 128);

    // ---------------- prologue: Ws(0), Ws(1), sign(0), dequant(0) ----------------
    cp16(sb + WS_OFF + wsdst0, stored + woff0);
    if (w1) cp16(sb + WS_OFF + wsdst0 + 8192, stored + woff1);
    cp_commit();                                            // Ws(0)
    cp16(sb + WS_OFF + 10240 + wsdst0, stored + woff0 + BK);
    if (w1) cp16(sb + WS_OFF + 10240 + wsdst0 + 8192, stored + woff1 + BK);
    cp_commit();                                            // Ws(1)
    uint4 rg0 = *(const uint4*)(sign + woff0);
    uint4 rg1 = w1 ? *(const uint4*)(sign + woff1) : make_uint4(0, 0, 0, 0);
    asm volatile("cp.async.wait_group 1;" ::: "memory");    // Ws(0) done
    __syncthreads();                                        // publish Ws(0) + LUT
    {
        uint32_t s0, s1, s2, s3x;
        lds128(sb + WS_OFF + wsdst0, s0, s1, s2, s3x);
        uint32_t h0 = lut_lane[s0 << 5] | (rg0.x & 0x8000u);
        uint32_t h1 = lut_lane[s1 << 5] | (rg0.y & 0x8000u);
        uint32_t h2 = lut_lane[s2 << 5] | (rg0.z & 0x8000u);
        uint32_t h3 = lut_lane[s3x << 5] | (rg0.w & 0x8000u);
        sts64(sb + WF_OFF + wfdst0, h0 | (h1 << 16), h2 | (h3 << 16));
        if (w1) {
            lds128(sb + WS_OFF + wsdst0 + 8192, s0, s1, s2, s3x);
            h0 = lut_lane[s0 << 5] | (rg1.x & 0x8000u);
            h1 = lut_lane[s1 << 5] | (rg1.y & 0x8000u);
            h2 = lut_lane[s2 << 5] | (rg1.z & 0x8000u);
            h3 = lut_lane[s3x << 5] | (rg1.w & 0x8000u);
            sts64(sb + WF_OFF + wfdst0 + 4096, h0 | (h1 << 16), h2 | (h3 << 16));
        }
    }

    int s3 = 0, s3b = 1, s3c = 2;   // Ws stage rotation: k, k+1, k+2
#pragma unroll 1
    for (int k = 0; k < NCHUNK; k++) {
        // B-frags for chunk k: 4 contiguous LDG.128/warp from L2, issued first
        uint4 bx[4];
        {
            const __half* pk = pB + (uint32_t)k * 16384;
#pragma unroll
            for (int nt = 0; nt < 4; nt++)
                bx[nt] = *(const uint4*)(pk + nt * 256);
        }
        // Ws(k+2) copies
        if (k + 2 < NCHUNK) {
            const uint32_t K2 = (uint32_t)(k + 2) * BK;
            const uint32_t wd = sb + WS_OFF + (uint32_t)s3c * 10240;
            cp16(wd + wsdst0, stored + woff0 + K2);
            if (w1) cp16(wd + wsdst0 + 8192, stored + woff1 + K2);
            cp_commit();
        }
        // sign(k+1)
        if (k + 1 < NCHUNK) {
            const uint32_t K1 = (uint32_t)(k + 1) * BK;
            rg0 = *(const uint4*)(sign + woff0 + K1);
            if (w1) rg1 = *(const uint4*)(sign + woff1 + K1);
        }
        if (k + 2 < NCHUNK)      asm volatile("cp.async.wait_group 1;" ::: "memory");
        else if (k + 1 < NCHUNK) asm volatile("cp.async.wait_group 0;" ::: "memory");
        __syncthreads();   // publish Wf(k) [written last iter] + Ws(k+1)

        // MMA(k): A via lds32 from Wf, B from registers
        {
            const uint32_t wfs = sb + WF_OFF + (uint32_t)(k & 1) * 5120;
#pragma unroll
            for (int kk = 0; kk < 2; kk++) {
                uint32_t a[5][4];
#pragma unroll
                for (int mt = 0; mt < 5; mt++) {
                    a[mt][0] = lds32(wfs + baseA[mt] + coff[2 * kk]);
                    a[mt][1] = lds32(wfs + baseA[mt] + 512 + coff[2 * kk]);
                    a[mt][2] = lds32(wfs + baseA[mt] + coff[2 * kk + 1]);
                    a[mt][3] = lds32(wfs + baseA[mt] + 512 + coff[2 * kk + 1]);
                }
#pragma unroll
                for (int nt = 0; nt < 4; nt++) {
                    uint32_t b0 = kk ? bx[nt].z : bx[nt].x;
                    uint32_t b1 = kk ? bx[nt].w : bx[nt].y;
#pragma unroll
                    for (int mt = 0; mt < 5; mt++) mma16816(acc[mt][nt], a[mt], b0, b1);
                }
            }
        }

        // dequant(k+1) -> Wf[(k+1)&1]
        if (k + 1 < NCHUNK) {
            const uint32_t wsb = sb + WS_OFF + (uint32_t)s3b * 10240;
            const uint32_t wfb = sb + WF_OFF + (uint32_t)((k + 1) & 1) * 5120;
            uint32_t s0, s1, s2, s3x;
            lds128(wsb + wsdst0, s0, s1, s2, s3x);
            uint32_t h0 = lut_lane[s0 << 5] | (rg0.x & 0x8000u);
            uint32_t h1 = lut_lane[s1 << 5] | (rg0.y & 0x8000u);
            uint32_t h2 = lut_lane[s2 << 5] | (rg0.z & 0x8000u);
            uint32_t h3 = lut_lane[s3x << 5] | (rg0.w & 0x8000u);
            sts64(wfb + wfdst0, h0 | (h1 << 16), h2 | (h3 << 16));
            if (w1) {
                lds128(wsb + wsdst0 + 8192, s0, s1, s2, s3x);
                h0 = lut_lane[s0 << 5] | (rg1.x & 0x8000u);
                h1 = lut_lane[s1 << 5] | (rg1.y & 0x8000u);
                h2 = lut_lane[s2 << 5] | (rg1.z & 0x8000u);
                h3 = lut_lane[s3x << 5] | (rg1.w & 0x8000u);
                sts64(wfb + wfdst0 + 4096, h0 | (h1 << 16), h2 | (h3 << 16));
            }
        }

        int t = s3; s3 = s3b; s3b = s3c; s3c = t;
    }

    // ---------------- epilogue ----------------
#pragma unroll
    for (int mt = 0; mt < 5; mt++) {
        int o_lo = o0 + mt * 16 + gid;
        int o_hi = o_lo + 8;
        int cl = o_lo < OUT_DIM ? o_lo : OUT_DIM - 1;
        int ch = o_hi < OUT_DIM ? o_hi : OUT_DIM - 1;
        float blo = bias[cl], slo = scale[cl];
        float bhi = bias[ch], shi = scale[ch];
#pragma unroll
        for (int nt = 0; nt < 4; nt++) {
            int b = n0 + nt * 8 + tig * 2;
            float* p0 = out + (size_t)b * OUT_DIM;
            float* p1 = p0 + OUT_DIM;
            if (o_lo < OUT_DIM) {
                p0[o_lo] = (acc[mt][nt][0] + blo) * slo;
                p1[o_lo] = (acc[mt][nt][1] + blo) * slo;
            }
            if (o_hi < OUT_DIM) {
                p0[o_hi] = (acc[mt][nt][2] + bhi) * shi;
                p1[o_hi] = (acc[mt][nt][3] + bhi) * shi;
            }
        }
    }
}

extern "C" void kernel_launch(void* const* d_in, const int* in_sizes, int n_in,
                              void* d_out, int out_size) {
    const float* x      = (const float*)d_in[0];
    const int*   stored = (const int*)d_in[1];
    const int*   sign   = (const int*)d_in[2];
    const float* lmin   = (const float*)d_in[3];
    const float* lmax   = (const float*)d_in[4];
    const float* scale  = (const float*)d_in[5];
    const float* bias   = (const float*)d_in[6];
    float* out = (float*)d_out;

    prep_kernel<<<(B_DIM * IN_DIM / 8 + 255) / 256, 256>>>(x, lmin, lmax);

    cudaFuncSetAttribute(qgemm_kernel,
                         cudaFuncAttributeMaxDynamicSharedMemorySize, SMEM_BYTES);
    qgemm_kernel<<<NTILES, THREADS, SMEM_BYTES>>>(stored, sign, scale, bias, out);
}